// round 3
// baseline (speedup 1.0000x reference)
#include <cuda_runtime.h>
#include <math.h>
#include <stdint.h>

#define D_MODEL 1024
#define NUM_HEADS 16
#define HEAD_DIM 64
#define BATCH 2
#define SEQ 2048
#define M_TOT (BATCH * SEQ)   // 4096

// ---------------- scratch (static device globals; no allocation) ----------------
__device__ float g_Q[(size_t)M_TOT * D_MODEL];
__device__ float g_K[(size_t)M_TOT * D_MODEL];
__device__ float g_V[(size_t)M_TOT * D_MODEL];
__device__ float g_A[(size_t)M_TOT * D_MODEL];

// ---------------- tf32 helpers ----------------
__device__ __forceinline__ uint32_t f2tf(float x) {
    uint32_t r;
    asm("cvt.rna.tf32.f32 %0, %1;" : "=r"(r) : "f"(x));
    return r;
}
__device__ __forceinline__ void split_tf(float x, uint32_t& hi, uint32_t& lo) {
    uint32_t h = f2tf(x);
    hi = h;
    lo = f2tf(x - __uint_as_float(h));
}
// D += A * B  (m16n8k8, tf32 inputs, f32 accum)
__device__ __forceinline__ void mma8(float* c, const uint32_t* a, const uint32_t* b) {
    asm volatile(
        "mma.sync.aligned.m16n8k8.row.col.f32.tf32.tf32.f32 "
        "{%0,%1,%2,%3}, {%4,%5,%6,%7}, {%8,%9}, {%0,%1,%2,%3};"
        : "+f"(c[0]), "+f"(c[1]), "+f"(c[2]), "+f"(c[3])
        : "r"(a[0]), "r"(a[1]), "r"(a[2]), "r"(a[3]), "r"(b[0]), "r"(b[1]));
}

// ---------------- projection GEMM: C[M,N] = A[M,K] @ W[N,K]^T  (3xTF32, fused RoPE) ----------
// BM=BN=128, BK=16, 256 threads = 8 warps, warp tile 64x32.
// A/B pre-split into hi/lo smem at load time -> inner loop is pure LDS + HMMA.
#define PJ_STR 20   // smem k-stride

template <bool ROPE>
__global__ __launch_bounds__(256)
void proj_kernel(const float* __restrict__ A,
                 const float* __restrict__ W,
                 float* __restrict__ C,
                 const int* __restrict__ tok)
{
    __shared__ uint32_t Ash[128 * PJ_STR];
    __shared__ uint32_t Asl[128 * PJ_STR];
    __shared__ uint32_t Bsh[128 * PJ_STR];
    __shared__ uint32_t Bsl[128 * PJ_STR];

    const int tid  = threadIdx.x;
    const int wid  = tid >> 5;
    const int lane = tid & 31;
    const int g = lane >> 2;     // 0..7
    const int t = lane & 3;      // 0..3
    const int wm = (wid & 1) * 64;
    const int wn = (wid >> 1) * 32;
    const int m0 = blockIdx.y * 128;
    const int n0 = blockIdx.x * 128;

    const int lrow = tid >> 1;
    const int lk   = (tid & 1) * 8;
    const float* Ag = A + (size_t)(m0 + lrow) * D_MODEL + lk;
    const float* Wg = W + (size_t)(n0 + lrow) * D_MODEL + lk;

    float acc[4][4][4];
#pragma unroll
    for (int i = 0; i < 4; i++)
#pragma unroll
        for (int j = 0; j < 4; j++)
#pragma unroll
            for (int r = 0; r < 4; r++) acc[i][j][r] = 0.0f;

    for (int k0 = 0; k0 < D_MODEL; k0 += 16) {
        float av[8], bv[8];
        *(float4*)&av[0] = *(const float4*)(Ag + k0);
        *(float4*)&av[4] = *(const float4*)(Ag + k0 + 4);
        *(float4*)&bv[0] = *(const float4*)(Wg + k0);
        *(float4*)&bv[4] = *(const float4*)(Wg + k0 + 4);
        __syncthreads();
#pragma unroll
        for (int i = 0; i < 8; i++) {
            uint32_t h, l;
            split_tf(av[i], h, l);
            Ash[lrow * PJ_STR + lk + i] = h;
            Asl[lrow * PJ_STR + lk + i] = l;
            split_tf(bv[i], h, l);
            Bsh[lrow * PJ_STR + lk + i] = h;
            Bsl[lrow * PJ_STR + lk + i] = l;
        }
        __syncthreads();

#pragma unroll
        for (int ks = 0; ks < 16; ks += 8) {
            uint32_t ah[4][4], al[4][4], bh[4][2], bl[4][2];
#pragma unroll
            for (int mi = 0; mi < 4; mi++) {
                int row = wm + mi * 16;
                ah[mi][0] = Ash[(row + g)     * PJ_STR + ks + t];
                ah[mi][1] = Ash[(row + g + 8) * PJ_STR + ks + t];
                ah[mi][2] = Ash[(row + g)     * PJ_STR + ks + t + 4];
                ah[mi][3] = Ash[(row + g + 8) * PJ_STR + ks + t + 4];
                al[mi][0] = Asl[(row + g)     * PJ_STR + ks + t];
                al[mi][1] = Asl[(row + g + 8) * PJ_STR + ks + t];
                al[mi][2] = Asl[(row + g)     * PJ_STR + ks + t + 4];
                al[mi][3] = Asl[(row + g + 8) * PJ_STR + ks + t + 4];
            }
#pragma unroll
            for (int nj = 0; nj < 4; nj++) {
                int col = wn + nj * 8;
                bh[nj][0] = Bsh[(col + g) * PJ_STR + ks + t];
                bh[nj][1] = Bsh[(col + g) * PJ_STR + ks + t + 4];
                bl[nj][0] = Bsl[(col + g) * PJ_STR + ks + t];
                bl[nj][1] = Bsl[(col + g) * PJ_STR + ks + t + 4];
            }
#pragma unroll
            for (int mi = 0; mi < 4; mi++)
#pragma unroll
                for (int nj = 0; nj < 4; nj++) {
                    mma8(acc[mi][nj], ah[mi], bl[nj]);
                    mma8(acc[mi][nj], al[mi], bh[nj]);
                    mma8(acc[mi][nj], ah[mi], bh[nj]);
                }
        }
    }

    // epilogue (+ fused RoPE)
#pragma unroll
    for (int mi = 0; mi < 4; mi++) {
#pragma unroll
        for (int nj = 0; nj < 4; nj++) {
            int row1 = m0 + wm + mi * 16 + g;
            int row2 = row1 + 8;
            int col  = n0 + wn + nj * 8 + 2 * t;   // even
            float c0 = acc[mi][nj][0], c1 = acc[mi][nj][1];
            float c2 = acc[mi][nj][2], c3 = acc[mi][nj][3];
            if (ROPE) {
                int hc = col & (HEAD_DIM - 1);
                float inv = expf(-0.14391156831212787f * (float)hc);
                float p1 = (float)tok[row1 & (SEQ - 1)];
                float p2 = (float)tok[row2 & (SEQ - 1)];
                float s1, co1, s2, co2;
                sincosf(p1 * inv, &s1, &co1);
                sincosf(p2 * inv, &s2, &co2);
                float e0 = c0, o0 = c1;
                c0 = e0 * co1 - o0 * s1;
                c1 = e0 * s1 + o0 * co1;
                float e2 = c2, o2 = c3;
                c2 = e2 * co2 - o2 * s2;
                c3 = e2 * s2 + o2 * co2;
            }
            *(float2*)(C + (size_t)row1 * D_MODEL + col) = make_float2(c0, c1);
            *(float2*)(C + (size_t)row2 * D_MODEL + col) = make_float2(c2, c3);
        }
    }
}

// ---------------- causal flash attention (tensor-core, 3xTF32) ----------------
// Block = 128 queries of one (b,h), 256 threads = 8 warps (warp w -> rows w*16..+15).
// K/V pre-split into hi/lo smem once per tile.
#define AT_STR 68
// smem floats: Kh,Kl,Vh,Vl: 4*64*AT_STR  Ss: 128*AT_STR  stats: 3*128
#define ATTN_SMEM_F (4 * 64 * AT_STR + 128 * AT_STR + 3 * 128)
#define ATTN_SMEM_B (ATTN_SMEM_F * sizeof(float))

__global__ __launch_bounds__(256)
void attn_kernel(const float* __restrict__ Q,
                 const float* __restrict__ K,
                 const float* __restrict__ V,
                 float* __restrict__ O)
{
    extern __shared__ float sm[];
    uint32_t* Kh = (uint32_t*)sm;                  // 64*AT_STR
    uint32_t* Kl = Kh + 64 * AT_STR;
    uint32_t* Vh = Kl + 64 * AT_STR;
    uint32_t* Vl = Vh + 64 * AT_STR;
    float* Ss    = (float*)(Vl + 64 * AT_STR);     // 128*AT_STR
    float* m_run = Ss + 128 * AT_STR;              // 128
    float* l_run = m_run + 128;
    float* scl   = l_run + 128;

    const int tid  = threadIdx.x;
    const int w    = tid >> 5;
    const int lane = tid & 31;
    const int g = lane >> 2;
    const int t = lane & 3;
    const int qt = blockIdx.x;
    const int h  = blockIdx.y;
    const int b  = blockIdx.z;
    const int q0 = qt * 128;
    const int qr = w * 16;

    if (tid < 128) { m_run[tid] = -1e30f; l_run[tid] = 0.0f; }

    const float* Qb = Q + (size_t)b * SEQ * D_MODEL + h * HEAD_DIM;
    const float* Kb = K + (size_t)b * SEQ * D_MODEL + h * HEAD_DIM;
    const float* Vb = V + (size_t)b * SEQ * D_MODEL + h * HEAD_DIM;

    // stage Q (pre-scaled by 1/sqrt(64)) into Ss, then lift split fragments to regs
    for (int i = tid; i < 128 * 16; i += 256) {
        int r = i >> 4, c4 = (i & 15) * 4;
        float4 v = *(const float4*)(Qb + (size_t)(q0 + r) * D_MODEL + c4);
        v.x *= 0.125f; v.y *= 0.125f; v.z *= 0.125f; v.w *= 0.125f;
        *(float4*)&Ss[r * AT_STR + c4] = v;
    }
    __syncthreads();

    uint32_t qh[8][4], ql[8][4];
#pragma unroll
    for (int ks = 0; ks < 8; ks++) {
        int kc = ks * 8;
        split_tf(Ss[(qr + g)     * AT_STR + kc + t],     qh[ks][0], ql[ks][0]);
        split_tf(Ss[(qr + g + 8) * AT_STR + kc + t],     qh[ks][1], ql[ks][1]);
        split_tf(Ss[(qr + g)     * AT_STR + kc + t + 4], qh[ks][2], ql[ks][2]);
        split_tf(Ss[(qr + g + 8) * AT_STR + kc + t + 4], qh[ks][3], ql[ks][3]);
    }
    __syncthreads();

    float oacc[8][4];
#pragma unroll
    for (int j = 0; j < 8; j++)
#pragma unroll
        for (int r = 0; r < 4; r++) oacc[j][r] = 0.0f;

    const int ntiles = 2 * qt + 2;     // keys [0, q0+128) in 64-key tiles
    for (int kt = 0; kt < ntiles; kt++) {
        const int k0 = kt * 64;
        // cooperative load + split of K/V tile
        for (int i = tid; i < 64 * 16; i += 256) {
            int r = i >> 4, c4 = (i & 15) * 4;
            float4 kv = *(const float4*)(Kb + (size_t)(k0 + r) * D_MODEL + c4);
            float4 vv = *(const float4*)(Vb + (size_t)(k0 + r) * D_MODEL + c4);
            int base = r * AT_STR + c4;
            uint32_t hh, ll;
            split_tf(kv.x, hh, ll); Kh[base + 0] = hh; Kl[base + 0] = ll;
            split_tf(kv.y, hh, ll); Kh[base + 1] = hh; Kl[base + 1] = ll;
            split_tf(kv.z, hh, ll); Kh[base + 2] = hh; Kl[base + 2] = ll;
            split_tf(kv.w, hh, ll); Kh[base + 3] = hh; Kl[base + 3] = ll;
            split_tf(vv.x, hh, ll); Vh[base + 0] = hh; Vl[base + 0] = ll;
            split_tf(vv.y, hh, ll); Vh[base + 1] = hh; Vl[base + 1] = ll;
            split_tf(vv.z, hh, ll); Vh[base + 2] = hh; Vl[base + 2] = ll;
            split_tf(vv.w, hh, ll); Vh[base + 3] = hh; Vl[base + 3] = ll;
        }
        __syncthreads();

        // ---- S = Q @ K^T ----
        float sacc[8][4];
#pragma unroll
        for (int j = 0; j < 8; j++)
#pragma unroll
            for (int r = 0; r < 4; r++) sacc[j][r] = 0.0f;

#pragma unroll
        for (int j = 0; j < 8; j++) {
            int key = j * 8 + g;
#pragma unroll
            for (int ks = 0; ks < 8; ks++) {
                int d = ks * 8 + t;
                uint32_t bh[2], bl[2];
                bh[0] = Kh[key * AT_STR + d];
                bh[1] = Kh[key * AT_STR + d + 4];
                bl[0] = Kl[key * AT_STR + d];
                bl[1] = Kl[key * AT_STR + d + 4];
                mma8(sacc[j], qh[ks], bl);
                mma8(sacc[j], ql[ks], bh);
                mma8(sacc[j], qh[ks], bh);
            }
        }
#pragma unroll
        for (int j = 0; j < 8; j++) {
            int c = j * 8 + 2 * t;
            *(float2*)&Ss[(qr + g)     * AT_STR + c] = make_float2(sacc[j][0], sacc[j][1]);
            *(float2*)&Ss[(qr + g + 8) * AT_STR + c] = make_float2(sacc[j][2], sacc[j][3]);
        }
        __syncthreads();

        // ---- online softmax: 2 threads per row (128 rows, 64 cols) ----
        {
            int row  = tid >> 1;
            int half = tid & 1;
            int qi   = q0 + row;
            int base = half * 32;
            float lm = -1e30f;
            for (int c = 0; c < 32; c++) {
                int col = base + c;
                float s = Ss[row * AT_STR + col];
                if (k0 + col <= qi) lm = fmaxf(lm, s);
            }
            float tm = fmaxf(lm, __shfl_xor_sync(0xffffffffu, lm, 1));
            float mo = m_run[row];
            float mn = fmaxf(mo, tm);
            float ls = 0.0f;
            for (int c = 0; c < 32; c++) {
                int col = base + c;
                float s = Ss[row * AT_STR + col];
                float p = (k0 + col <= qi) ? __expf(s - mn) : 0.0f;
                Ss[row * AT_STR + col] = p;
                ls += p;
            }
            ls += __shfl_xor_sync(0xffffffffu, ls, 1);
            if (half == 0) {
                float sc = __expf(mo - mn);
                scl[row]   = sc;
                l_run[row] = l_run[row] * sc + ls;
                m_run[row] = mn;
            }
        }
        __syncthreads();

        // ---- rescale O, then O += P @ V ----
        {
            float sa = scl[qr + g];
            float sb = scl[qr + g + 8];
#pragma unroll
            for (int j = 0; j < 8; j++) {
                oacc[j][0] *= sa; oacc[j][1] *= sa;
                oacc[j][2] *= sb; oacc[j][3] *= sb;
            }
        }
#pragma unroll
        for (int ks = 0; ks < 8; ks++) {
            int kk = ks * 8;
            uint32_t ah[4], al[4];
            split_tf(Ss[(qr + g)     * AT_STR + kk + t],     ah[0], al[0]);
            split_tf(Ss[(qr + g + 8) * AT_STR + kk + t],     ah[1], al[1]);
            split_tf(Ss[(qr + g)     * AT_STR + kk + t + 4], ah[2], al[2]);
            split_tf(Ss[(qr + g + 8) * AT_STR + kk + t + 4], ah[3], al[3]);
#pragma unroll
            for (int j = 0; j < 8; j++) {
                uint32_t bh[2], bl[2];
                bh[0] = Vh[(kk + t)     * AT_STR + j * 8 + g];
                bh[1] = Vh[(kk + t + 4) * AT_STR + j * 8 + g];
                bl[0] = Vl[(kk + t)     * AT_STR + j * 8 + g];
                bl[1] = Vl[(kk + t + 4) * AT_STR + j * 8 + g];
                mma8(oacc[j], ah, bl);
                mma8(oacc[j], al, bh);
                mma8(oacc[j], ah, bh);
            }
        }
        __syncthreads();   // protect smem for next tile
    }

    // ---- epilogue: normalize + store ----
    float ia = 1.0f / l_run[qr + g];
    float ib = 1.0f / l_run[qr + g + 8];
    float* Ob = O + ((size_t)b * SEQ + q0) * D_MODEL + h * HEAD_DIM;
#pragma unroll
    for (int j = 0; j < 8; j++) {
        int c = j * 8 + 2 * t;
        *(float2*)&Ob[(size_t)(qr + g) * D_MODEL + c] =
            make_float2(oacc[j][0] * ia, oacc[j][1] * ia);
        *(float2*)&Ob[(size_t)(qr + g + 8) * D_MODEL + c] =
            make_float2(oacc[j][2] * ib, oacc[j][3] * ib);
    }
}

// ---------------- launch ----------------
extern "C" void kernel_launch(void* const* d_in, const int* in_sizes, int n_in,
                              void* d_out, int out_size)
{
    const float* x   = (const float*)d_in[0];
    const int*   tok = (const int*)d_in[1];
    const float* wq  = (const float*)d_in[2];
    const float* wk  = (const float*)d_in[3];
    const float* wv  = (const float*)d_in[4];
    const float* wo  = (const float*)d_in[5];
    float* out = (float*)d_out;

    float *Qb, *Kb, *Vb, *Ab;
    cudaGetSymbolAddress((void**)&Qb, g_Q);
    cudaGetSymbolAddress((void**)&Kb, g_K);
    cudaGetSymbolAddress((void**)&Vb, g_V);
    cudaGetSymbolAddress((void**)&Ab, g_A);

    dim3 pgrid(D_MODEL / 128, M_TOT / 128);   // (8, 32)

    proj_kernel<true ><<<pgrid, 256>>>(x, wq, Qb, tok);
    proj_kernel<true ><<<pgrid, 256>>>(x, wk, Kb, tok);
    proj_kernel<false><<<pgrid, 256>>>(x, wv, Vb, nullptr);

    cudaFuncSetAttribute(attn_kernel,
                         cudaFuncAttributeMaxDynamicSharedMemorySize,
                         (int)ATTN_SMEM_B);
    attn_kernel<<<dim3(SEQ / 128, NUM_HEADS, BATCH), 256, ATTN_SMEM_B>>>(Qb, Kb, Vb, Ab);

    proj_kernel<false><<<pgrid, 256>>>(Ab, wo, out, nullptr);
}

// round 4
// speedup vs baseline: 1.3410x; 1.3410x over previous
#include <cuda_runtime.h>
#include <math.h>
#include <stdint.h>

#define D_MODEL 1024
#define NUM_HEADS 16
#define HEAD_DIM 64
#define BATCH 2
#define SEQ 2048
#define M_TOT (BATCH * SEQ)   // 4096

// ---------------- scratch (static device globals; no allocation) ----------------
__device__ float g_Q[(size_t)M_TOT * D_MODEL];
__device__ float g_K[(size_t)M_TOT * D_MODEL];
__device__ float g_V[(size_t)M_TOT * D_MODEL];
__device__ float g_A[(size_t)M_TOT * D_MODEL];

// ---------------- helpers ----------------
__device__ __forceinline__ uint32_t f2tf(float x) {
    uint32_t r;
    asm("cvt.rna.tf32.f32 %0, %1;" : "=r"(r) : "f"(x));
    return r;
}
__device__ __forceinline__ void split_tf(float x, uint32_t& hi, uint32_t& lo) {
    uint32_t h = f2tf(x);
    hi = h;
    lo = f2tf(x - __uint_as_float(h));
}
__device__ __forceinline__ void mma8(float* c, const uint32_t* a, const uint32_t* b) {
    asm volatile(
        "mma.sync.aligned.m16n8k8.row.col.f32.tf32.tf32.f32 "
        "{%0,%1,%2,%3}, {%4,%5,%6,%7}, {%8,%9}, {%0,%1,%2,%3};"
        : "+f"(c[0]), "+f"(c[1]), "+f"(c[2]), "+f"(c[3])
        : "r"(a[0]), "r"(a[1]), "r"(a[2]), "r"(a[3]), "r"(b[0]), "r"(b[1]));
}
__device__ __forceinline__ uint32_t s2u(const void* p) {
    return (uint32_t)__cvta_generic_to_shared(p);
}
__device__ __forceinline__ void ldsm4(uint32_t& r0, uint32_t& r1, uint32_t& r2,
                                      uint32_t& r3, uint32_t addr) {
    asm volatile("ldmatrix.sync.aligned.m8n8.x4.shared.b16 {%0,%1,%2,%3}, [%4];"
                 : "=r"(r0), "=r"(r1), "=r"(r2), "=r"(r3) : "r"(addr));
}
__device__ __forceinline__ void cpa16(uint32_t dst, const void* src) {
    asm volatile("cp.async.cg.shared.global [%0], [%1], 16;" :: "r"(dst), "l"(src));
}
#define CP_COMMIT() asm volatile("cp.async.commit_group;")
#define CP_WAIT1()  asm volatile("cp.async.wait_group 1;" ::: "memory")

// ---------------- projection GEMM (3xTF32, pre-split smem + ldmatrix) ----------------
// C[M,N] = A[M,K] @ W[N,K]^T. BM=BN=128, BK=16, 256 thr = 8 warps, warp 64x32.
// gridDim.z selects W/C (fused QKV); RoPE if tok != null and z < 2.
#define PJ_STR 20

__global__ __launch_bounds__(256, 2)
void proj_kernel(const float* __restrict__ A,
                 const float* __restrict__ W0, const float* __restrict__ W1,
                 const float* __restrict__ W2,
                 float* __restrict__ C0, float* __restrict__ C1,
                 float* __restrict__ C2,
                 const int* __restrict__ tok)
{
    __shared__ uint32_t Ash[128 * PJ_STR];
    __shared__ uint32_t Asl[128 * PJ_STR];
    __shared__ uint32_t Bsh[128 * PJ_STR];
    __shared__ uint32_t Bsl[128 * PJ_STR];

    const int z = blockIdx.z;
    const float* W = (z == 0) ? W0 : (z == 1) ? W1 : W2;
    float* C       = (z == 0) ? C0 : (z == 1) ? C1 : C2;
    const bool rope = (tok != nullptr) && (z < 2);

    const int tid  = threadIdx.x;
    const int wid  = tid >> 5;
    const int lane = tid & 31;
    const int g = lane >> 2;
    const int t = lane & 3;
    const int wm = (wid & 1) * 64;
    const int wn = (wid >> 1) * 32;
    const int m0 = blockIdx.y * 128;
    const int n0 = blockIdx.x * 128;

    const int lrow = tid >> 1;
    const int lk   = (tid & 1) * 8;
    const float* Ag = A + (size_t)(m0 + lrow) * D_MODEL + lk;
    const float* Wg = W + (size_t)(n0 + lrow) * D_MODEL + lk;

    // ldmatrix per-lane address components
    const int ar    = (lane & 7) + ((lane >> 3) & 1) * 8;   // A row-in-16
    const int acoff = (lane >> 4) * 4;                       // A col half
    const int bro   = (lane & 7);                            // B row-in-8
    const int bnsel = (lane >> 4);                           // B nj select in pair
    const int bcoff = ((lane >> 3) & 1) * 4;                 // B col half

    const uint32_t aH = s2u(Ash), aL = s2u(Asl), bH = s2u(Bsh), bL = s2u(Bsl);
    const uint32_t aOff = (uint32_t)(((wm + ar) * PJ_STR + acoff) * 4);
    // B pair p base row: wn + (2p + bnsel)*8 + bro
    uint32_t bOff[2];
#pragma unroll
    for (int p = 0; p < 2; p++)
        bOff[p] = (uint32_t)(((wn + (2 * p + bnsel) * 8 + bro) * PJ_STR + bcoff) * 4);

    float acc[4][4][4];
#pragma unroll
    for (int i = 0; i < 4; i++)
#pragma unroll
        for (int j = 0; j < 4; j++)
#pragma unroll
            for (int r = 0; r < 4; r++) acc[i][j][r] = 0.0f;

    float av[8], bv[8];
    *(float4*)&av[0] = *(const float4*)(Ag);
    *(float4*)&av[4] = *(const float4*)(Ag + 4);
    *(float4*)&bv[0] = *(const float4*)(Wg);
    *(float4*)&bv[4] = *(const float4*)(Wg + 4);

    for (int k0 = 0; k0 < D_MODEL; k0 += 16) {
        __syncthreads();
        {
            uint32_t h[8], l[8], h2[8], l2[8];
#pragma unroll
            for (int i = 0; i < 8; i++) {
                split_tf(av[i], h[i], l[i]);
                split_tf(bv[i], h2[i], l2[i]);
            }
            int base = lrow * PJ_STR + lk;
            *(uint4*)&Ash[base]     = make_uint4(h[0], h[1], h[2], h[3]);
            *(uint4*)&Ash[base + 4] = make_uint4(h[4], h[5], h[6], h[7]);
            *(uint4*)&Asl[base]     = make_uint4(l[0], l[1], l[2], l[3]);
            *(uint4*)&Asl[base + 4] = make_uint4(l[4], l[5], l[6], l[7]);
            *(uint4*)&Bsh[base]     = make_uint4(h2[0], h2[1], h2[2], h2[3]);
            *(uint4*)&Bsh[base + 4] = make_uint4(h2[4], h2[5], h2[6], h2[7]);
            *(uint4*)&Bsl[base]     = make_uint4(l2[0], l2[1], l2[2], l2[3]);
            *(uint4*)&Bsl[base + 4] = make_uint4(l2[4], l2[5], l2[6], l2[7]);
        }
        if (k0 + 16 < D_MODEL) {
            *(float4*)&av[0] = *(const float4*)(Ag + k0 + 16);
            *(float4*)&av[4] = *(const float4*)(Ag + k0 + 20);
            *(float4*)&bv[0] = *(const float4*)(Wg + k0 + 16);
            *(float4*)&bv[4] = *(const float4*)(Wg + k0 + 20);
        }
        __syncthreads();

#pragma unroll
        for (int ksi = 0; ksi < 2; ksi++) {
            const uint32_t ksb = (uint32_t)(ksi * 8 * 4);
            uint32_t bh[4][2], bl[4][2];
            ldsm4(bh[0][0], bh[0][1], bh[1][0], bh[1][1], bH + bOff[0] + ksb);
            ldsm4(bh[2][0], bh[2][1], bh[3][0], bh[3][1], bH + bOff[1] + ksb);
            ldsm4(bl[0][0], bl[0][1], bl[1][0], bl[1][1], bL + bOff[0] + ksb);
            ldsm4(bl[2][0], bl[2][1], bl[3][0], bl[3][1], bL + bOff[1] + ksb);
#pragma unroll
            for (int mi = 0; mi < 4; mi++) {
                const uint32_t mo = aOff + (uint32_t)(mi * 16 * PJ_STR * 4) + ksb;
                uint32_t ah[4], al[4];
                ldsm4(ah[0], ah[1], ah[2], ah[3], aH + mo);
                ldsm4(al[0], al[1], al[2], al[3], aL + mo);
#pragma unroll
                for (int nj = 0; nj < 4; nj++) {
                    mma8(acc[mi][nj], ah, bl[nj]);
                    mma8(acc[mi][nj], al, bh[nj]);
                    mma8(acc[mi][nj], ah, bh[nj]);
                }
            }
        }
    }

    // epilogue (+ fused RoPE)
#pragma unroll
    for (int mi = 0; mi < 4; mi++) {
#pragma unroll
        for (int nj = 0; nj < 4; nj++) {
            int row1 = m0 + wm + mi * 16 + g;
            int row2 = row1 + 8;
            int col  = n0 + wn + nj * 8 + 2 * t;
            float c0 = acc[mi][nj][0], c1 = acc[mi][nj][1];
            float c2 = acc[mi][nj][2], c3 = acc[mi][nj][3];
            if (rope) {
                int hc = col & (HEAD_DIM - 1);
                float inv = expf(-0.14391156831212787f * (float)hc);
                float p1 = (float)tok[row1 & (SEQ - 1)];
                float p2 = (float)tok[row2 & (SEQ - 1)];
                float s1, co1, s2, co2;
                sincosf(p1 * inv, &s1, &co1);
                sincosf(p2 * inv, &s2, &co2);
                float e0 = c0, o0 = c1;
                c0 = e0 * co1 - o0 * s1;
                c1 = e0 * s1 + o0 * co1;
                float e2 = c2, o2 = c3;
                c2 = e2 * co2 - o2 * s2;
                c3 = e2 * s2 + o2 * co2;
            }
            *(float2*)(C + (size_t)row1 * D_MODEL + col) = make_float2(c0, c1);
            *(float2*)(C + (size_t)row2 * D_MODEL + col) = make_float2(c2, c3);
        }
    }
}

// ---------------- causal flash attention (3xTF32, register softmax) ----------------
// Block = 64 queries of one (b,h), 128 threads = 4 warps (warp w -> rows w*16..+15).
// K/V double-buffered via cp.async; softmax entirely in registers.
#define AT_STR 68
#define TILE_F (64 * AT_STR)
#define ATTN_SMEM_B (4 * TILE_F * sizeof(float))

__global__ void __launch_bounds__(128, 3)
attn_kernel(const float* __restrict__ Q,
            const float* __restrict__ K,
            const float* __restrict__ V,
            float* __restrict__ O)
{
    extern __shared__ float sm[];   // [buf0 K | buf0 V | buf1 K | buf1 V]

    const int tid  = threadIdx.x;
    const int w    = tid >> 5;
    const int lane = tid & 31;
    const int g = lane >> 2;
    const int t = lane & 3;
    const int qt = blockIdx.x;
    const int h  = blockIdx.y;
    const int b  = blockIdx.z;
    const int q0 = qt * 64;
    const int qr = w * 16;

    const float* Qb = Q + (size_t)b * SEQ * D_MODEL + h * HEAD_DIM;
    const float* Kb = K + (size_t)b * SEQ * D_MODEL + h * HEAD_DIM;
    const float* Vb = V + (size_t)b * SEQ * D_MODEL + h * HEAD_DIM;

    // ---- stage Q (scaled) into buf1 K-area, lift split fragments to registers ----
    float* Qs = sm + 2 * TILE_F;
    for (int i = tid; i < 64 * 16; i += 128) {
        int r = i >> 4, c4 = (i & 15) * 4;
        float4 v = *(const float4*)(Qb + (size_t)(q0 + r) * D_MODEL + c4);
        v.x *= 0.125f; v.y *= 0.125f; v.z *= 0.125f; v.w *= 0.125f;
        *(float4*)&Qs[r * AT_STR + c4] = v;
    }
    __syncthreads();

    uint32_t qh[8][4], ql[8][4];
    {
        const int mrow = qr + (lane & 7) + ((lane >> 3) & 1) * 8;
        const int mcol = (lane >> 4) * 4;
        const uint32_t qbase = s2u(Qs);
#pragma unroll
        for (int ks = 0; ks < 8; ks++) {
            uint32_t r0, r1, r2, r3;
            ldsm4(r0, r1, r2, r3,
                  qbase + (uint32_t)(((mrow) * AT_STR + ks * 8 + mcol) * 4));
            split_tf(__uint_as_float(r0), qh[ks][0], ql[ks][0]);
            split_tf(__uint_as_float(r1), qh[ks][1], ql[ks][1]);
            split_tf(__uint_as_float(r2), qh[ks][2], ql[ks][2]);
            split_tf(__uint_as_float(r3), qh[ks][3], ql[ks][3]);
        }
    }

    // ---- prologue: tile 0 -> buf0 ----
    {
        float* Kd = sm;
        float* Vd = sm + TILE_F;
        uint32_t kd = s2u(Kd), vd = s2u(Vd);
#pragma unroll
        for (int i = 0; i < 8; i++) {
            int idx = tid + i * 128;
            int r = idx >> 4, c4 = (idx & 15) * 4;
            uint32_t off = (uint32_t)((r * AT_STR + c4) * 4);
            cpa16(kd + off, Kb + (size_t)r * D_MODEL + c4);
            cpa16(vd + off, Vb + (size_t)r * D_MODEL + c4);
        }
        CP_COMMIT();
    }

    float oacc[8][4];
#pragma unroll
    for (int j = 0; j < 8; j++)
#pragma unroll
        for (int r = 0; r < 4; r++) oacc[j][r] = 0.0f;
    float mA = -1e30f, lA = 0.0f, mB = -1e30f, lB = 0.0f;

    const int ntiles = qt + 1;
    for (int kt = 0; kt < ntiles; kt++) {
        const int k0 = kt * 64;
        float* Ks = sm + (kt & 1) * 2 * TILE_F;
        float* Vs = Ks + TILE_F;

        __syncthreads();   // all warps done reading buf[(kt+1)&1]
        if (kt + 1 < ntiles) {
            float* Kd = sm + ((kt + 1) & 1) * 2 * TILE_F;
            float* Vd = Kd + TILE_F;
            uint32_t kd = s2u(Kd), vd = s2u(Vd);
            const int kn = (kt + 1) * 64;
#pragma unroll
            for (int i = 0; i < 8; i++) {
                int idx = tid + i * 128;
                int r = idx >> 4, c4 = (idx & 15) * 4;
                uint32_t off = (uint32_t)((r * AT_STR + c4) * 4);
                cpa16(kd + off, Kb + (size_t)(kn + r) * D_MODEL + c4);
                cpa16(vd + off, Vb + (size_t)(kn + r) * D_MODEL + c4);
            }
        }
        CP_COMMIT();
        CP_WAIT1();
        __syncthreads();   // tile kt visible to all warps

        // ---- S = Q @ K^T ----
        float sacc[8][4];
#pragma unroll
        for (int j = 0; j < 8; j++)
#pragma unroll
            for (int r = 0; r < 4; r++) sacc[j][r] = 0.0f;

        {
            const uint32_t kbase = s2u(Ks);
            const int brow = (lane & 7);
            const int bch  = (lane >> 3);
#pragma unroll
            for (int j = 0; j < 8; j++) {
                uint32_t kraw[16];
#pragma unroll
                for (int cg = 0; cg < 4; cg++) {
                    uint32_t addr = kbase +
                        (uint32_t)(((j * 8 + brow) * AT_STR + (4 * cg + bch) * 4) * 4);
                    ldsm4(kraw[4 * cg], kraw[4 * cg + 1], kraw[4 * cg + 2],
                          kraw[4 * cg + 3], addr);
                }
#pragma unroll
                for (int ks = 0; ks < 8; ks++) {
                    uint32_t bh[2], bl[2];
                    split_tf(__uint_as_float(kraw[2 * ks]),     bh[0], bl[0]);
                    split_tf(__uint_as_float(kraw[2 * ks + 1]), bh[1], bl[1]);
                    mma8(sacc[j], qh[ks], bl);
                    mma8(sacc[j], ql[ks], bh);
                    mma8(sacc[j], qh[ks], bh);
                }
            }
        }

        // ---- causal mask (warp-uniform skip for interior tiles) ----
        if (k0 + 63 > q0 + qr) {
            const int rowA = q0 + qr + g;
            const int rowB = rowA + 8;
#pragma unroll
            for (int j = 0; j < 8; j++) {
                int colb = k0 + j * 8 + 2 * t;
                if (colb     > rowA) sacc[j][0] = -1e30f;
                if (colb + 1 > rowA) sacc[j][1] = -1e30f;
                if (colb     > rowB) sacc[j][2] = -1e30f;
                if (colb + 1 > rowB) sacc[j][3] = -1e30f;
            }
        }

        // ---- register online softmax (reduce across 4-lane t-group) ----
        float mtA = -1e30f, mtB = -1e30f;
#pragma unroll
        for (int j = 0; j < 8; j++) {
            mtA = fmaxf(mtA, fmaxf(sacc[j][0], sacc[j][1]));
            mtB = fmaxf(mtB, fmaxf(sacc[j][2], sacc[j][3]));
        }
        mtA = fmaxf(mtA, __shfl_xor_sync(0xffffffffu, mtA, 1));
        mtA = fmaxf(mtA, __shfl_xor_sync(0xffffffffu, mtA, 2));
        mtB = fmaxf(mtB, __shfl_xor_sync(0xffffffffu, mtB, 1));
        mtB = fmaxf(mtB, __shfl_xor_sync(0xffffffffu, mtB, 2));
        float mnA = fmaxf(mA, mtA), mnB = fmaxf(mB, mtB);
        float aA = __expf(mA - mnA), aB = __expf(mB - mnB);
        float sA = 0.0f, sB = 0.0f;
#pragma unroll
        for (int j = 0; j < 8; j++) {
            sacc[j][0] = __expf(sacc[j][0] - mnA);
            sacc[j][1] = __expf(sacc[j][1] - mnA);
            sacc[j][2] = __expf(sacc[j][2] - mnB);
            sacc[j][3] = __expf(sacc[j][3] - mnB);
            sA += sacc[j][0] + sacc[j][1];
            sB += sacc[j][2] + sacc[j][3];
        }
        sA += __shfl_xor_sync(0xffffffffu, sA, 1);
        sA += __shfl_xor_sync(0xffffffffu, sA, 2);
        sB += __shfl_xor_sync(0xffffffffu, sB, 1);
        sB += __shfl_xor_sync(0xffffffffu, sB, 2);
        lA = lA * aA + sA; mA = mnA;
        lB = lB * aB + sB; mB = mnB;
#pragma unroll
        for (int j = 0; j < 8; j++) {
            oacc[j][0] *= aA; oacc[j][1] *= aA;
            oacc[j][2] *= aB; oacc[j][3] *= aB;
        }

        // ---- O += P @ V  (P fragments gathered via shuffles) ----
        const int srcA = (lane & ~3) | (t >> 1);
        const int srcB = srcA + 2;
        const bool odd = (t & 1);
#pragma unroll
        for (int ks = 0; ks < 8; ks++) {
            const int kk = ks * 8;
            float v00 = __shfl_sync(0xffffffffu, sacc[ks][0], srcA);
            float v01 = __shfl_sync(0xffffffffu, sacc[ks][1], srcA);
            float v02 = __shfl_sync(0xffffffffu, sacc[ks][2], srcA);
            float v03 = __shfl_sync(0xffffffffu, sacc[ks][3], srcA);
            float v10 = __shfl_sync(0xffffffffu, sacc[ks][0], srcB);
            float v11 = __shfl_sync(0xffffffffu, sacc[ks][1], srcB);
            float v12 = __shfl_sync(0xffffffffu, sacc[ks][2], srcB);
            float v13 = __shfl_sync(0xffffffffu, sacc[ks][3], srcB);
            uint32_t ah[4], al[4];
            split_tf(odd ? v01 : v00, ah[0], al[0]);   // row A, col kk+t
            split_tf(odd ? v03 : v02, ah[1], al[1]);   // row B, col kk+t
            split_tf(odd ? v11 : v10, ah[2], al[2]);   // row A, col kk+t+4
            split_tf(odd ? v13 : v12, ah[3], al[3]);   // row B, col kk+t+4
            const float* vr0 = Vs + (kk + t) * AT_STR;
            const float* vr1 = Vs + (kk + t + 4) * AT_STR;
#pragma unroll
            for (int j = 0; j < 8; j++) {
                uint32_t bh[2], bl[2];
                split_tf(vr0[j * 8 + g], bh[0], bl[0]);
                split_tf(vr1[j * 8 + g], bh[1], bl[1]);
                mma8(oacc[j], ah, bl);
                mma8(oacc[j], al, bh);
                mma8(oacc[j], ah, bh);
            }
        }
    }

    // ---- epilogue ----
    float ia = 1.0f / lA;
    float ib = 1.0f / lB;
    float* Ob = O + ((size_t)b * SEQ + q0) * D_MODEL + h * HEAD_DIM;
#pragma unroll
    for (int j = 0; j < 8; j++) {
        int c = j * 8 + 2 * t;
        *(float2*)&Ob[(size_t)(qr + g) * D_MODEL + c] =
            make_float2(oacc[j][0] * ia, oacc[j][1] * ia);
        *(float2*)&Ob[(size_t)(qr + g + 8) * D_MODEL + c] =
            make_float2(oacc[j][2] * ib, oacc[j][3] * ib);
    }
}

// ---------------- launch ----------------
extern "C" void kernel_launch(void* const* d_in, const int* in_sizes, int n_in,
                              void* d_out, int out_size)
{
    const float* x   = (const float*)d_in[0];
    const int*   tok = (const int*)d_in[1];
    const float* wq  = (const float*)d_in[2];
    const float* wk  = (const float*)d_in[3];
    const float* wv  = (const float*)d_in[4];
    const float* wo  = (const float*)d_in[5];
    float* out = (float*)d_out;

    float *Qb, *Kb, *Vb, *Ab;
    cudaGetSymbolAddress((void**)&Qb, g_Q);
    cudaGetSymbolAddress((void**)&Kb, g_K);
    cudaGetSymbolAddress((void**)&Vb, g_V);
    cudaGetSymbolAddress((void**)&Ab, g_A);

    // fused Q/K/V projections
    proj_kernel<<<dim3(D_MODEL / 128, M_TOT / 128, 3), 256>>>(
        x, wq, wk, wv, Qb, Kb, Vb, tok);

    cudaFuncSetAttribute(attn_kernel,
                         cudaFuncAttributeMaxDynamicSharedMemorySize,
                         (int)ATTN_SMEM_B);
    attn_kernel<<<dim3(SEQ / 64, NUM_HEADS, BATCH), 128, ATTN_SMEM_B>>>(Qb, Kb, Vb, Ab);

    // output projection
    proj_kernel<<<dim3(D_MODEL / 128, M_TOT / 128, 1), 256>>>(
        Ab, wo, wo, wo, out, out, out, nullptr);
}

// round 13
// speedup vs baseline: 1.6075x; 1.1988x over previous
#include <cuda_runtime.h>
#include <math.h>
#include <stdint.h>

#define D_MODEL 1024
#define NUM_HEADS 16
#define HEAD_DIM 64
#define BATCH 2
#define SEQ 2048
#define M_TOT (BATCH * SEQ)   // 4096

// ---------------- scratch (static device globals; no allocation) ----------------
__device__ float g_Q[(size_t)M_TOT * D_MODEL];
__device__ float g_K[(size_t)M_TOT * D_MODEL];
__device__ float g_V[(size_t)M_TOT * D_MODEL];
__device__ float g_A[(size_t)M_TOT * D_MODEL];

// ---------------- helpers ----------------
__device__ __forceinline__ uint32_t f2tf(float x) {
    uint32_t r;
    asm("cvt.rna.tf32.f32 %0, %1;" : "=r"(r) : "f"(x));
    return r;
}
__device__ __forceinline__ void split_tf(float x, uint32_t& hi, uint32_t& lo) {
    uint32_t h = f2tf(x);
    hi = h;
    lo = f2tf(x - __uint_as_float(h));
}
__device__ __forceinline__ void mma8(float* c, const uint32_t* a, const uint32_t* b) {
    asm volatile(
        "mma.sync.aligned.m16n8k8.row.col.f32.tf32.tf32.f32 "
        "{%0,%1,%2,%3}, {%4,%5,%6,%7}, {%8,%9}, {%0,%1,%2,%3};"
        : "+f"(c[0]), "+f"(c[1]), "+f"(c[2]), "+f"(c[3])
        : "r"(a[0]), "r"(a[1]), "r"(a[2]), "r"(a[3]), "r"(b[0]), "r"(b[1]));
}
__device__ __forceinline__ uint32_t s2u(const void* p) {
    return (uint32_t)__cvta_generic_to_shared(p);
}
__device__ __forceinline__ void ldsm4(uint32_t& r0, uint32_t& r1, uint32_t& r2,
                                      uint32_t& r3, uint32_t addr) {
    asm volatile("ldmatrix.sync.aligned.m8n8.x4.shared.b16 {%0,%1,%2,%3}, [%4];"
                 : "=r"(r0), "=r"(r1), "=r"(r2), "=r"(r3) : "r"(addr));
}
__device__ __forceinline__ void cpa16(uint32_t dst, const void* src) {
    asm volatile("cp.async.cg.shared.global [%0], [%1], 16;" :: "r"(dst), "l"(src));
}
#define CP_COMMIT() asm volatile("cp.async.commit_group;")
#define CP_WAIT1()  asm volatile("cp.async.wait_group 1;" ::: "memory")

// ---------------- projection GEMM (3xTF32, double-buffered split smem) ----------------
// C[M,N] = A[M,K] @ W[N,K]^T. BM=BN=128, BK=16, 256 thr = 8 warps, warp 64x32.
// gridDim.z selects W/C (fused QKV); RoPE if tok != null and z < 2.
#define PJ_STR 20
#define PJ_ARR (128 * PJ_STR)                 // u32 per array (2560)
#define PJ_STAGE (4 * PJ_ARR)                 // u32 per stage (Ash,Asl,Bsh,Bsl)
#define PJ_SMEM_B (2 * PJ_STAGE * sizeof(uint32_t))   // 81920 bytes

__global__ __launch_bounds__(256, 2)
void proj_kernel(const float* __restrict__ A,
                 const float* __restrict__ W0, const float* __restrict__ W1,
                 const float* __restrict__ W2,
                 float* __restrict__ C0, float* __restrict__ C1,
                 float* __restrict__ C2,
                 const int* __restrict__ tok)
{
    extern __shared__ uint32_t psm[];

    const int z = blockIdx.z;
    const float* W = (z == 0) ? W0 : (z == 1) ? W1 : W2;
    float* C       = (z == 0) ? C0 : (z == 1) ? C1 : C2;
    const bool rope = (tok != nullptr) && (z < 2);

    const int tid  = threadIdx.x;
    const int wid  = tid >> 5;
    const int lane = tid & 31;
    const int g = lane >> 2;
    const int t = lane & 3;
    const int wm = (wid & 1) * 64;
    const int wn = (wid >> 1) * 32;
    const int m0 = blockIdx.y * 128;
    const int n0 = blockIdx.x * 128;

    const int lrow = tid >> 1;
    const int lk   = (tid & 1) * 8;
    const float* Ag = A + (size_t)(m0 + lrow) * D_MODEL + lk;
    const float* Wg = W + (size_t)(n0 + lrow) * D_MODEL + lk;

    // ldmatrix per-lane address components
    const int ar    = (lane & 7) + ((lane >> 3) & 1) * 8;
    const int acoff = (lane >> 4) * 4;
    const int bro   = (lane & 7);
    const int bnsel = (lane >> 4);
    const int bcoff = ((lane >> 3) & 1) * 4;

    const uint32_t smbase = s2u(psm);
    const uint32_t aOff = (uint32_t)(((wm + ar) * PJ_STR + acoff) * 4);
    uint32_t bOff[2];
#pragma unroll
    for (int p = 0; p < 2; p++)
        bOff[p] = (uint32_t)(((wn + (2 * p + bnsel) * 8 + bro) * PJ_STR + bcoff) * 4);

    float acc[4][4][4];
#pragma unroll
    for (int i = 0; i < 4; i++)
#pragma unroll
        for (int j = 0; j < 4; j++)
#pragma unroll
            for (int r = 0; r < 4; r++) acc[i][j][r] = 0.0f;

    float av[8], bv[8];
    *(float4*)&av[0] = *(const float4*)(Ag);
    *(float4*)&av[4] = *(const float4*)(Ag + 4);
    *(float4*)&bv[0] = *(const float4*)(Wg);
    *(float4*)&bv[4] = *(const float4*)(Wg + 4);

    int it = 0;
    for (int k0 = 0; k0 < D_MODEL; k0 += 16, it ^= 1) {
        // split + STS into stage `it` (safe: consumers of this stage finished
        // before sync of previous iteration — 2-stage distance)
        {
            uint32_t* Ash = psm + it * PJ_STAGE;
            uint32_t* Asl = Ash + PJ_ARR;
            uint32_t* Bsh = Asl + PJ_ARR;
            uint32_t* Bsl = Bsh + PJ_ARR;
            uint32_t h[8], l[8], h2[8], l2[8];
#pragma unroll
            for (int i = 0; i < 8; i++) {
                split_tf(av[i], h[i], l[i]);
                split_tf(bv[i], h2[i], l2[i]);
            }
            int base = lrow * PJ_STR + lk;
            *(uint4*)&Ash[base]     = make_uint4(h[0], h[1], h[2], h[3]);
            *(uint4*)&Ash[base + 4] = make_uint4(h[4], h[5], h[6], h[7]);
            *(uint4*)&Asl[base]     = make_uint4(l[0], l[1], l[2], l[3]);
            *(uint4*)&Asl[base + 4] = make_uint4(l[4], l[5], l[6], l[7]);
            *(uint4*)&Bsh[base]     = make_uint4(h2[0], h2[1], h2[2], h2[3]);
            *(uint4*)&Bsh[base + 4] = make_uint4(h2[4], h2[5], h2[6], h2[7]);
            *(uint4*)&Bsl[base]     = make_uint4(l2[0], l2[1], l2[2], l2[3]);
            *(uint4*)&Bsl[base + 4] = make_uint4(l2[4], l2[5], l2[6], l2[7]);
        }
        __syncthreads();
        if (k0 + 16 < D_MODEL) {
            *(float4*)&av[0] = *(const float4*)(Ag + k0 + 16);
            *(float4*)&av[4] = *(const float4*)(Ag + k0 + 20);
            *(float4*)&bv[0] = *(const float4*)(Wg + k0 + 16);
            *(float4*)&bv[4] = *(const float4*)(Wg + k0 + 20);
        }

        const uint32_t sb = smbase + (uint32_t)(it * PJ_STAGE * 4);
        const uint32_t aH = sb, aL = sb + PJ_ARR * 4;
        const uint32_t bH = sb + 2 * PJ_ARR * 4, bL = sb + 3 * PJ_ARR * 4;
#pragma unroll
        for (int ksi = 0; ksi < 2; ksi++) {
            const uint32_t ksb = (uint32_t)(ksi * 8 * 4);
            uint32_t bh[4][2], bl[4][2];
            ldsm4(bh[0][0], bh[0][1], bh[1][0], bh[1][1], bH + bOff[0] + ksb);
            ldsm4(bh[2][0], bh[2][1], bh[3][0], bh[3][1], bH + bOff[1] + ksb);
            ldsm4(bl[0][0], bl[0][1], bl[1][0], bl[1][1], bL + bOff[0] + ksb);
            ldsm4(bl[2][0], bl[2][1], bl[3][0], bl[3][1], bL + bOff[1] + ksb);
#pragma unroll
            for (int mi = 0; mi < 4; mi++) {
                const uint32_t mo = aOff + (uint32_t)(mi * 16 * PJ_STR * 4) + ksb;
                uint32_t ah[4], al[4];
                ldsm4(ah[0], ah[1], ah[2], ah[3], aH + mo);
                ldsm4(al[0], al[1], al[2], al[3], aL + mo);
#pragma unroll
                for (int nj = 0; nj < 4; nj++) {
                    mma8(acc[mi][nj], ah, bl[nj]);
                    mma8(acc[mi][nj], al, bh[nj]);
                    mma8(acc[mi][nj], ah, bh[nj]);
                }
            }
        }
    }

    // epilogue (+ fused RoPE)
#pragma unroll
    for (int mi = 0; mi < 4; mi++) {
#pragma unroll
        for (int nj = 0; nj < 4; nj++) {
            int row1 = m0 + wm + mi * 16 + g;
            int row2 = row1 + 8;
            int col  = n0 + wn + nj * 8 + 2 * t;
            float c0 = acc[mi][nj][0], c1 = acc[mi][nj][1];
            float c2 = acc[mi][nj][2], c3 = acc[mi][nj][3];
            if (rope) {
                int hc = col & (HEAD_DIM - 1);
                float inv = expf(-0.14391156831212787f * (float)hc);
                float p1 = (float)tok[row1 & (SEQ - 1)];
                float p2 = (float)tok[row2 & (SEQ - 1)];
                float s1, co1, s2, co2;
                sincosf(p1 * inv, &s1, &co1);
                sincosf(p2 * inv, &s2, &co2);
                float e0 = c0, o0 = c1;
                c0 = e0 * co1 - o0 * s1;
                c1 = e0 * s1 + o0 * co1;
                float e2 = c2, o2 = c3;
                c2 = e2 * co2 - o2 * s2;
                c3 = e2 * s2 + o2 * co2;
            }
            *(float2*)(C + (size_t)row1 * D_MODEL + col) = make_float2(c0, c1);
            *(float2*)(C + (size_t)row2 * D_MODEL + col) = make_float2(c2, c3);
        }
    }
}

// ---------------- causal flash attention (QK 3xTF32, PV 1xTF32, register softmax) ----
// Block = 64 queries of one (b,h), 128 threads = 4 warps (warp w -> rows w*16..+15).
// K/V double-buffered via cp.async; softmax entirely in registers.
#define AT_STR 68
#define TILE_F (64 * AT_STR)
#define ATTN_SMEM_B (4 * TILE_F * sizeof(float))

__global__ void __launch_bounds__(128, 3)
attn_kernel(const float* __restrict__ Q,
            const float* __restrict__ K,
            const float* __restrict__ V,
            float* __restrict__ O)
{
    extern __shared__ float sm[];   // [buf0 K | buf0 V | buf1 K | buf1 V]

    const int tid  = threadIdx.x;
    const int w    = tid >> 5;
    const int lane = tid & 31;
    const int g = lane >> 2;
    const int t = lane & 3;
    const int qt = blockIdx.x;
    const int h  = blockIdx.y;
    const int b  = blockIdx.z;
    const int q0 = qt * 64;
    const int qr = w * 16;

    const float* Qb = Q + (size_t)b * SEQ * D_MODEL + h * HEAD_DIM;
    const float* Kb = K + (size_t)b * SEQ * D_MODEL + h * HEAD_DIM;
    const float* Vb = V + (size_t)b * SEQ * D_MODEL + h * HEAD_DIM;

    // ---- stage Q (scaled) into buf1 K-area, lift split fragments to registers ----
    float* Qs = sm + 2 * TILE_F;
    for (int i = tid; i < 64 * 16; i += 128) {
        int r = i >> 4, c4 = (i & 15) * 4;
        float4 v = *(const float4*)(Qb + (size_t)(q0 + r) * D_MODEL + c4);
        v.x *= 0.125f; v.y *= 0.125f; v.z *= 0.125f; v.w *= 0.125f;
        *(float4*)&Qs[r * AT_STR + c4] = v;
    }
    __syncthreads();

    uint32_t qh[8][4], ql[8][4];
    {
        const int mrow = qr + (lane & 7) + ((lane >> 3) & 1) * 8;
        const int mcol = (lane >> 4) * 4;
        const uint32_t qbase = s2u(Qs);
#pragma unroll
        for (int ks = 0; ks < 8; ks++) {
            uint32_t r0, r1, r2, r3;
            ldsm4(r0, r1, r2, r3,
                  qbase + (uint32_t)(((mrow) * AT_STR + ks * 8 + mcol) * 4));
            split_tf(__uint_as_float(r0), qh[ks][0], ql[ks][0]);
            split_tf(__uint_as_float(r1), qh[ks][1], ql[ks][1]);
            split_tf(__uint_as_float(r2), qh[ks][2], ql[ks][2]);
            split_tf(__uint_as_float(r3), qh[ks][3], ql[ks][3]);
        }
    }

    // ---- prologue: tile 0 -> buf0 ----
    {
        float* Kd = sm;
        float* Vd = sm + TILE_F;
        uint32_t kd = s2u(Kd), vd = s2u(Vd);
#pragma unroll
        for (int i = 0; i < 8; i++) {
            int idx = tid + i * 128;
            int r = idx >> 4, c4 = (idx & 15) * 4;
            uint32_t off = (uint32_t)((r * AT_STR + c4) * 4);
            cpa16(kd + off, Kb + (size_t)r * D_MODEL + c4);
            cpa16(vd + off, Vb + (size_t)r * D_MODEL + c4);
        }
        CP_COMMIT();
    }

    float oacc[8][4];
#pragma unroll
    for (int j = 0; j < 8; j++)
#pragma unroll
        for (int r = 0; r < 4; r++) oacc[j][r] = 0.0f;
    float mA = -1e30f, lA = 0.0f, mB = -1e30f, lB = 0.0f;

    const int ntiles = qt + 1;
    for (int kt = 0; kt < ntiles; kt++) {
        const int k0 = kt * 64;
        float* Ks = sm + (kt & 1) * 2 * TILE_F;
        float* Vs = Ks + TILE_F;

        __syncthreads();   // all warps done reading buf[(kt+1)&1]
        if (kt + 1 < ntiles) {
            float* Kd = sm + ((kt + 1) & 1) * 2 * TILE_F;
            float* Vd = Kd + TILE_F;
            uint32_t kd = s2u(Kd), vd = s2u(Vd);
            const int kn = (kt + 1) * 64;
#pragma unroll
            for (int i = 0; i < 8; i++) {
                int idx = tid + i * 128;
                int r = idx >> 4, c4 = (idx & 15) * 4;
                uint32_t off = (uint32_t)((r * AT_STR + c4) * 4);
                cpa16(kd + off, Kb + (size_t)(kn + r) * D_MODEL + c4);
                cpa16(vd + off, Vb + (size_t)(kn + r) * D_MODEL + c4);
            }
        }
        CP_COMMIT();
        CP_WAIT1();
        __syncthreads();   // tile kt visible to all warps

        // ---- S = Q @ K^T (3-term TF32) ----
        float sacc[8][4];
#pragma unroll
        for (int j = 0; j < 8; j++)
#pragma unroll
            for (int r = 0; r < 4; r++) sacc[j][r] = 0.0f;

        {
            const uint32_t kbase = s2u(Ks);
            const int brow = (lane & 7);
            const int bch  = (lane >> 3);
#pragma unroll
            for (int j = 0; j < 8; j++) {
                uint32_t kraw[16];
#pragma unroll
                for (int cg = 0; cg < 4; cg++) {
                    uint32_t addr = kbase +
                        (uint32_t)(((j * 8 + brow) * AT_STR + (4 * cg + bch) * 4) * 4);
                    ldsm4(kraw[4 * cg], kraw[4 * cg + 1], kraw[4 * cg + 2],
                          kraw[4 * cg + 3], addr);
                }
#pragma unroll
                for (int ks = 0; ks < 8; ks++) {
                    uint32_t bh[2], bl[2];
                    split_tf(__uint_as_float(kraw[2 * ks]),     bh[0], bl[0]);
                    split_tf(__uint_as_float(kraw[2 * ks + 1]), bh[1], bl[1]);
                    mma8(sacc[j], qh[ks], bl);
                    mma8(sacc[j], ql[ks], bh);
                    mma8(sacc[j], qh[ks], bh);
                }
            }
        }

        // ---- causal mask (warp-uniform skip for interior tiles) ----
        if (k0 + 63 > q0 + qr) {
            const int rowA = q0 + qr + g;
            const int rowB = rowA + 8;
#pragma unroll
            for (int j = 0; j < 8; j++) {
                int colb = k0 + j * 8 + 2 * t;
                if (colb     > rowA) sacc[j][0] = -1e30f;
                if (colb + 1 > rowA) sacc[j][1] = -1e30f;
                if (colb     > rowB) sacc[j][2] = -1e30f;
                if (colb + 1 > rowB) sacc[j][3] = -1e30f;
            }
        }

        // ---- register online softmax (reduce across 4-lane t-group) ----
        float mtA = -1e30f, mtB = -1e30f;
#pragma unroll
        for (int j = 0; j < 8; j++) {
            mtA = fmaxf(mtA, fmaxf(sacc[j][0], sacc[j][1]));
            mtB = fmaxf(mtB, fmaxf(sacc[j][2], sacc[j][3]));
        }
        mtA = fmaxf(mtA, __shfl_xor_sync(0xffffffffu, mtA, 1));
        mtA = fmaxf(mtA, __shfl_xor_sync(0xffffffffu, mtA, 2));
        mtB = fmaxf(mtB, __shfl_xor_sync(0xffffffffu, mtB, 1));
        mtB = fmaxf(mtB, __shfl_xor_sync(0xffffffffu, mtB, 2));
        float mnA = fmaxf(mA, mtA), mnB = fmaxf(mB, mtB);
        float aA = __expf(mA - mnA), aB = __expf(mB - mnB);
        float sA = 0.0f, sB = 0.0f;
#pragma unroll
        for (int j = 0; j < 8; j++) {
            sacc[j][0] = __expf(sacc[j][0] - mnA);
            sacc[j][1] = __expf(sacc[j][1] - mnA);
            sacc[j][2] = __expf(sacc[j][2] - mnB);
            sacc[j][3] = __expf(sacc[j][3] - mnB);
            sA += sacc[j][0] + sacc[j][1];
            sB += sacc[j][2] + sacc[j][3];
        }
        sA += __shfl_xor_sync(0xffffffffu, sA, 1);
        sA += __shfl_xor_sync(0xffffffffu, sA, 2);
        sB += __shfl_xor_sync(0xffffffffu, sB, 1);
        sB += __shfl_xor_sync(0xffffffffu, sB, 2);
        lA = lA * aA + sA; mA = mnA;
        lB = lB * aB + sB; mB = mnB;
#pragma unroll
        for (int j = 0; j < 8; j++) {
            oacc[j][0] *= aA; oacc[j][1] *= aA;
            oacc[j][2] *= aB; oacc[j][3] *= aB;
        }

        // ---- O += P @ V  (single-term TF32; P fragments via shuffles) ----
        const int srcA = (lane & ~3) | (t >> 1);
        const int srcB = srcA + 2;
        const bool odd = (t & 1);
#pragma unroll
        for (int ks = 0; ks < 8; ks++) {
            const int kk = ks * 8;
            float v00 = __shfl_sync(0xffffffffu, sacc[ks][0], srcA);
            float v01 = __shfl_sync(0xffffffffu, sacc[ks][1], srcA);
            float v02 = __shfl_sync(0xffffffffu, sacc[ks][2], srcA);
            float v03 = __shfl_sync(0xffffffffu, sacc[ks][3], srcA);
            float v10 = __shfl_sync(0xffffffffu, sacc[ks][0], srcB);
            float v11 = __shfl_sync(0xffffffffu, sacc[ks][1], srcB);
            float v12 = __shfl_sync(0xffffffffu, sacc[ks][2], srcB);
            float v13 = __shfl_sync(0xffffffffu, sacc[ks][3], srcB);
            uint32_t ap[4];
            ap[0] = f2tf(odd ? v01 : v00);   // row A, col kk+t
            ap[1] = f2tf(odd ? v03 : v02);   // row B, col kk+t
            ap[2] = f2tf(odd ? v11 : v10);   // row A, col kk+t+4
            ap[3] = f2tf(odd ? v13 : v12);   // row B, col kk+t+4
            const float* vr0 = Vs + (kk + t) * AT_STR;
            const float* vr1 = Vs + (kk + t + 4) * AT_STR;
#pragma unroll
            for (int j = 0; j < 8; j++) {
                uint32_t bb[2];
                bb[0] = f2tf(vr0[j * 8 + g]);
                bb[1] = f2tf(vr1[j * 8 + g]);
                mma8(oacc[j], ap, bb);
            }
        }
    }

    // ---- epilogue ----
    float ia = 1.0f / lA;
    float ib = 1.0f / lB;
    float* Ob = O + ((size_t)b * SEQ + q0) * D_MODEL + h * HEAD_DIM;
#pragma unroll
    for (int j = 0; j < 8; j++) {
        int c = j * 8 + 2 * t;
        *(float2*)&Ob[(size_t)(qr + g) * D_MODEL + c] =
            make_float2(oacc[j][0] * ia, oacc[j][1] * ia);
        *(float2*)&Ob[(size_t)(qr + g + 8) * D_MODEL + c] =
            make_float2(oacc[j][2] * ib, oacc[j][3] * ib);
    }
}

// ---------------- launch ----------------
extern "C" void kernel_launch(void* const* d_in, const int* in_sizes, int n_in,
                              void* d_out, int out_size)
{
    const float* x   = (const float*)d_in[0];
    const int*   tok = (const int*)d_in[1];
    const float* wq  = (const float*)d_in[2];
    const float* wk  = (const float*)d_in[3];
    const float* wv  = (const float*)d_in[4];
    const float* wo  = (const float*)d_in[5];
    float* out = (float*)d_out;

    float *Qb, *Kb, *Vb, *Ab;
    cudaGetSymbolAddress((void**)&Qb, g_Q);
    cudaGetSymbolAddress((void**)&Kb, g_K);
    cudaGetSymbolAddress((void**)&Vb, g_V);
    cudaGetSymbolAddress((void**)&Ab, g_A);

    cudaFuncSetAttribute(proj_kernel,
                         cudaFuncAttributeMaxDynamicSharedMemorySize,
                         (int)PJ_SMEM_B);
    cudaFuncSetAttribute(attn_kernel,
                         cudaFuncAttributeMaxDynamicSharedMemorySize,
                         (int)ATTN_SMEM_B);

    // fused Q/K/V projections
    proj_kernel<<<dim3(D_MODEL / 128, M_TOT / 128, 3), 256, PJ_SMEM_B>>>(
        x, wq, wk, wv, Qb, Kb, Vb, tok);

    attn_kernel<<<dim3(SEQ / 64, NUM_HEADS, BATCH), 128, ATTN_SMEM_B>>>(Qb, Kb, Vb, Ab);

    // output projection
    proj_kernel<<<dim3(D_MODEL / 128, M_TOT / 128, 1), 256, PJ_SMEM_B>>>(
        Ab, wo, wo, wo, out, out, out, nullptr);
}